// round 1
// baseline (speedup 1.0000x reference)
#include <cuda_runtime.h>
#include <math.h>

// Problem constants
#define NN        512          // feature dim n
#define ROWS      256          // B*S = 2*128
#define BM        32
#define BN        32
#define BK        32
#define NB_GEMM   128          // (ROWS/BM)*(NN/BN) = 8*16
#define NB_FILL   1024
#define THREADS   256

// Output layout (tuple flattened in order): sample[256*512], mu[256*512], std_mat[256*512*512]
#define SAMPLE_ELEMS 131072
#define STD_QUADS    16777216u   // 67108864 floats / 4

__global__ __launch_bounds__(THREADS)
void gaussian_sampler_fused(const float* __restrict__ x,
                            const float* __restrict__ W,
                            const float* __restrict__ b,
                            const float* __restrict__ eps,
                            float* __restrict__ out)
{
    float* __restrict__ outS = out;                       // sample
    float* __restrict__ outM = out + SAMPLE_ELEMS;        // mu
    float* __restrict__ outD = out + 2 * SAMPLE_ELEMS;    // std_mat (diag)

    if (blockIdx.x >= NB_GEMM) {
        // ------------------ FILL ROLE: zero std_mat except diagonal lanes ------------------
        const unsigned fb = blockIdx.x - NB_GEMM;
        const unsigned stride = NB_FILL * THREADS;
        const float4 z = make_float4(0.f, 0.f, 0.f, 0.f);
        for (unsigned q = fb * THREADS + threadIdx.x; q < STD_QUADS; q += stride) {
            // q indexes float4 quads of std_mat. Each matrix-row has 128 quads.
            unsigned rowAll = q >> 7;        // global row index: (b*S+s)*512 + i
            unsigned c4     = q & 127u;      // quad column within the 512-wide row
            unsigned i      = rowAll & 511u; // i within the 512x512 matrix
            if ((i >> 2) == c4) {
                // diagonal-containing quad: write 3 zero lanes, leave diag lane to GEMM role
                float* p = outD + ((size_t)q << 2);
                unsigned l = i & 3u;
                if (l != 0u) p[0] = 0.f;
                if (l != 1u) p[1] = 0.f;
                if (l != 2u) p[2] = 0.f;
                if (l != 3u) p[3] = 0.f;
            } else {
                reinterpret_cast<float4*>(outD)[q] = z;
            }
        }
        return;
    }

    // ------------------ GEMM ROLE ------------------
    // C[row, m] = sum_k x[row,k] * W[m,k] + b[m];  var cols m=n (n in [0,512)), mu cols m=n+512.
    __shared__ float Xs[BM][BK + 1];
    __shared__ float Wv[BN][BK + 1];
    __shared__ float Wm[BN][BK + 1];

    const int bm   = blockIdx.x >> 4;     // 8 row tiles
    const int bn   = blockIdx.x & 15;     // 16 n tiles
    const int row0 = bm * BM;
    const int n0   = bn * BN;

    const int tid = threadIdx.x;
    const int tx  = tid & 15;             // 16 threads along n
    const int ty  = tid >> 4;             // 16 threads along rows
    const int rl  = ty * 2;               // local row base (2 rows per thread)
    const int nl  = tx * 2;               // local n base (2 cols per thread)

    // gmem staging mapping: each thread loads one float4 per tile
    const int lr = tid >> 3;              // 0..31 row within tile
    const int lc = (tid & 7) * 4;         // float4 column offset

    float av[2][2] = {{0.f,0.f},{0.f,0.f}};   // var-pre accumulators
    float am[2][2] = {{0.f,0.f},{0.f,0.f}};   // mu accumulators

    for (int k0 = 0; k0 < NN; k0 += BK) {
        float4 xv = *reinterpret_cast<const float4*>(&x[(size_t)(row0 + lr) * NN + k0 + lc]);
        Xs[lr][lc + 0] = xv.x; Xs[lr][lc + 1] = xv.y;
        Xs[lr][lc + 2] = xv.z; Xs[lr][lc + 3] = xv.w;

        float4 wv = *reinterpret_cast<const float4*>(&W[(size_t)(n0 + lr) * NN + k0 + lc]);
        Wv[lr][lc + 0] = wv.x; Wv[lr][lc + 1] = wv.y;
        Wv[lr][lc + 2] = wv.z; Wv[lr][lc + 3] = wv.w;

        float4 wm = *reinterpret_cast<const float4*>(&W[(size_t)(512 + n0 + lr) * NN + k0 + lc]);
        Wm[lr][lc + 0] = wm.x; Wm[lr][lc + 1] = wm.y;
        Wm[lr][lc + 2] = wm.z; Wm[lr][lc + 3] = wm.w;

        __syncthreads();

        #pragma unroll
        for (int kk = 0; kk < BK; kk++) {
            float x0 = Xs[rl][kk],     x1 = Xs[rl + 1][kk];
            float v0 = Wv[nl][kk],     v1 = Wv[nl + 1][kk];
            float m0 = Wm[nl][kk],     m1 = Wm[nl + 1][kk];
            av[0][0] += x0 * v0;  av[0][1] += x0 * v1;
            av[1][0] += x1 * v0;  av[1][1] += x1 * v1;
            am[0][0] += x0 * m0;  am[0][1] += x0 * m1;
            am[1][0] += x1 * m0;  am[1][1] += x1 * m1;
        }
        __syncthreads();
    }

    #pragma unroll
    for (int rr = 0; rr < 2; rr++) {
        #pragma unroll
        for (int nn = 0; nn < 2; nn++) {
            const int row = row0 + rl + rr;
            const int n   = n0 + nl + nn;
            float v  = av[rr][nn] + b[n];
            float m  = am[rr][nn] + b[512 + n];
            // softplus = log(1+exp(v)), overflow-safe
            float sp = (v > 20.f) ? v : log1pf(expf(v));
            const int idx = row * NN + n;
            outM[idx] = m;
            outS[idx] = m + sqrtf(sp) * eps[idx];
            outD[(size_t)idx * NN + n] = sp;   // diagonal of std_mat
        }
    }
}

extern "C" void kernel_launch(void* const* d_in, const int* in_sizes, int n_in,
                              void* d_out, int out_size)
{
    const float* x   = (const float*)d_in[0];   // (2,128,512)
    const float* W   = (const float*)d_in[1];   // (1024,512)
    const float* b   = (const float*)d_in[2];   // (1024,)
    const float* eps = (const float*)d_in[3];   // (2,128,512)
    float* out = (float*)d_out;

    (void)in_sizes; (void)n_in; (void)out_size;

    gaussian_sampler_fused<<<NB_GEMM + NB_FILL, THREADS>>>(x, W, b, eps, out);
}